// round 9
// baseline (speedup 1.0000x reference)
#include <cuda_runtime.h>
#include <cstdint>

#define HF 64
#define WF 64
#define CC 256
#define NB 4
#define KK 2048

// NHWC feature map: [N][64][64][C] = 16 MB
__device__ float g_nhwc[NB * HF * WF * CC];
// Row-pair max:  H1[n][h2][w][c]  = max over rows {2h2, 2h2+1}          (8 MB)
__device__ float g_h1[NB * (HF / 2) * WF * CC];
// Col-pair max:  W1[n][h][w2][c]  = max over cols {2w2, 2w2+1}          (8 MB)
__device__ float g_w1[NB * HF * (WF / 2) * CC];
// 2x2 block max: HW[n][h2][w2][c]                                        (4 MB)
__device__ float g_hw[NB * (HF / 2) * (WF / 2) * CC];

// ---------------------------------------------------------------------------
// Kernel 1: NCHW -> NHWC transpose via 32x32 smem tiles, coalesced both sides.
// ---------------------------------------------------------------------------
__global__ void transpose_nchw_nhwc(const float* __restrict__ in) {
    __shared__ float tile[32][33];
    const int n  = blockIdx.z;
    const int c0 = blockIdx.y * 32;
    const int s0 = blockIdx.x * 32;

    const float* inp = in + (size_t)n * CC * (HF * WF);
#pragma unroll
    for (int i = 0; i < 32; i += 8) {
        tile[threadIdx.y + i][threadIdx.x] =
            inp[(size_t)(c0 + threadIdx.y + i) * (HF * WF) + s0 + threadIdx.x];
    }
    __syncthreads();

    float* outp = g_nhwc + (size_t)n * (HF * WF) * CC;
#pragma unroll
    for (int i = 0; i < 32; i += 8) {
        outp[(size_t)(s0 + threadIdx.y + i) * CC + c0 + threadIdx.x] =
            tile[threadIdx.x][threadIdx.y + i];
    }
}

__device__ __forceinline__ float4 fmax4(float4 a, float4 b) {
    a.x = fmaxf(a.x, b.x);
    a.y = fmaxf(a.y, b.y);
    a.z = fmaxf(a.z, b.z);
    a.w = fmaxf(a.w, b.w);
    return a;
}

// ---------------------------------------------------------------------------
// Kernel 1b: fused pyramid build. One thread per 2x2 block per channel-group:
// reads 4 orig float4, writes 2 H1 + 2 W1 + 1 HW. All accesses coalesced
// (consecutive threads = consecutive channel groups).
// ---------------------------------------------------------------------------
__global__ void build_pyramid() {
    const int i = blockIdx.x * blockDim.x + threadIdx.x;
    const int total = NB * (HF / 2) * (WF / 2) * (CC / 4);   // 262144
    if (i >= total) return;
    const int g   = i & 63;            // channel group
    const int w2  = (i >> 6) & 31;
    const int h2  = (i >> 11) & 31;
    const int n   = i >> 16;

    const float4* src = (const float4*)g_nhwc +
        ((size_t)((n * HF + 2 * h2) * WF + 2 * w2)) * 64 + g;
    float4 a00 = src[0];
    float4 a01 = src[64];                       // w+1
    float4 a10 = src[(size_t)WF * 64];          // h+1
    float4 a11 = src[(size_t)WF * 64 + 64];

    float4 r0 = fmax4(a00, a10);    // rows paired, col 2w2
    float4 r1 = fmax4(a01, a11);    // rows paired, col 2w2+1
    float4 c0 = fmax4(a00, a01);    // cols paired, row 2h2
    float4 c1 = fmax4(a10, a11);    // cols paired, row 2h2+1

    float4* h1 = (float4*)g_h1 + ((size_t)((n * (HF / 2) + h2) * WF + 2 * w2)) * 64 + g;
    h1[0]  = r0;
    h1[64] = r1;

    float4* w1 = (float4*)g_w1 + ((size_t)((n * HF + 2 * h2) * (WF / 2) + w2)) * 64 + g;
    w1[0] = c0;
    w1[(size_t)(WF / 2) * 64] = c1;

    ((float4*)g_hw)[((size_t)((n * (HF / 2) + h2) * (WF / 2) + w2)) * 64 + g] =
        fmax4(r0, r1);
}

// Scan one row over [ws,we): odd lead col from fine, col-pairs from coarse,
// odd tail col from fine. fine indexed by w*64, coarse by w2*64.
__device__ __forceinline__ void scan_row(const float4* __restrict__ fine,
                                         const float4* __restrict__ coarse,
                                         int ws, int we,
                                         float4& m0, float4& m1) {
    int w = ws;
    if (w < we && (w & 1)) {
        m0 = fmax4(m0, __ldg(fine + (size_t)w * 64));
        ++w;
    }
    if (w < we) {
        const int rem    = we - w;          // >= 1
        int       w2     = w >> 1;
        const int w2end  = w2 + (rem >> 1);
        for (; w2 + 2 <= w2end; w2 += 2) {
            float4 a = __ldg(coarse + (size_t)w2 * 64);
            float4 c = __ldg(coarse + (size_t)(w2 + 1) * 64);
            m0 = fmax4(m0, a);
            m1 = fmax4(m1, c);
        }
        if (w2 < w2end) m1 = fmax4(m1, __ldg(coarse + (size_t)w2 * 64));
        if (rem & 1)    m0 = fmax4(m0, __ldg(fine + (size_t)(we - 1) * 64));
    }
}

// ---------------------------------------------------------------------------
// Kernel 2: RoI max pool with full 2D max pyramid.
//   grid = (2 channel-halves, 2048 rois), block = 256 threads
//   cg = tid&31 (4 channels, float4), sl = tid>>5 (warp-uniform bin slice)
// h-range: odd lead row (orig/W1) + row-pairs (H1/HW) + tail row (orig/W1);
// each row scanned with the col-pair decomposition above.
// ---------------------------------------------------------------------------
__global__ __launch_bounds__(256, 6)
void roipool_kernel(const float* __restrict__ rois, float* __restrict__ out) {
    __shared__ float sres[128 * 49];

    const int k    = blockIdx.y;
    const int half = blockIdx.x;
    const int tid  = threadIdx.x;
    const int cg   = tid & 31;
    const int sl   = tid >> 5;

    const float* r = rois + (size_t)k * 5;
    const int b   = (int)r[0];
    const int rsw = __float2int_rn(r[1] * 0.0625f);  // round-half-even == jnp.round
    const int rsh = __float2int_rn(r[2] * 0.0625f);
    const int rew = __float2int_rn(r[3] * 0.0625f);
    const int reh = __float2int_rn(r[4] * 0.0625f);
    const int roi_w = max(rew - rsw + 1, 1);
    const int roi_h = max(reh - rsh + 1, 1);

    // Reciprocal-multiply division matches the reference's XLA lowering
    // (verified R2: rel_err == 0). Do not change to exact divide.
    const float RCP7  = 1.0f / 7.0f;
    const float bin_h = (float)roi_h * RCP7;
    const float bin_w = (float)roi_w * RCP7;

    const int coff = half * 32 + cg;
    const float4* base   = (const float4*)g_nhwc + (size_t)b * (HF * WF) * 64 + coff;
    const float4* baseh  = (const float4*)g_h1  + (size_t)b * ((HF / 2) * WF) * 64 + coff;
    const float4* basew  = (const float4*)g_w1  + (size_t)b * (HF * (WF / 2)) * 64 + coff;
    const float4* basehw = (const float4*)g_hw  + (size_t)b * ((HF / 2) * (WF / 2)) * 64 + coff;

    const float NEG_INF = __int_as_float(0xff800000);

    int bi           = (49 * sl) >> 3;        // 6,6,6,6,6,6,6,7 bins/slice
    const int bi_end = (49 * (sl + 1)) >> 3;

    for (; bi < bi_end; ++bi) {
        const int ph = bi / 7;
        const int pw = bi - ph * 7;

        int hstart = (int)floorf((float)ph * bin_h) + rsh;
        int hend   = (int)ceilf((float)(ph + 1) * bin_h) + rsh;
        hstart = min(max(hstart, 0), HF);
        hend   = min(max(hend, 0), HF);

        int wstart = (int)floorf((float)pw * bin_w) + rsw;
        int wend   = (int)ceilf((float)(pw + 1) * bin_w) + rsw;
        wstart = min(max(wstart, 0), WF);
        wend   = min(max(wend, 0), WF);

        float4 m0 = make_float4(NEG_INF, NEG_INF, NEG_INF, NEG_INF);
        float4 m1 = m0;

        int h = hstart;
        // odd lead row: fine = orig row, coarse = W1 row
        if (h < hend && (h & 1)) {
            scan_row(base + (size_t)h * (WF * 64),
                     basew + (size_t)h * ((WF / 2) * 64),
                     wstart, wend, m0, m1);
            ++h;
        }
        // aligned row-pairs: fine = H1 row, coarse = HW row
        for (; h + 2 <= hend; h += 2) {
            const int h2 = h >> 1;
            scan_row(baseh + (size_t)h2 * (WF * 64),
                     basehw + (size_t)h2 * ((WF / 2) * 64),
                     wstart, wend, m0, m1);
        }
        // tail row: fine = orig row, coarse = W1 row
        if (h < hend) {
            scan_row(base + (size_t)h * (WF * 64),
                     basew + (size_t)h * ((WF / 2) * 64),
                     wstart, wend, m0, m1);
        }

        float4 m = fmax4(m0, m1);
        if (!((hstart < hend) && (wstart < wend)))
            m = make_float4(0.f, 0.f, 0.f, 0.f);

        const int cbase = 4 * cg;
        sres[(cbase + 0) * 49 + bi] = m.x;
        sres[(cbase + 1) * 49 + bi] = m.y;
        sres[(cbase + 2) * 49 + bi] = m.z;
        sres[(cbase + 3) * 49 + bi] = m.w;
    }
    __syncthreads();

    // Contiguous coalesced flush: block owns output span
    // [k*12544 + half*6272, +6272) = 1568 float4.
    float4* outv = (float4*)(out + (size_t)k * (CC * 49) + (size_t)half * (128 * 49));
    const float4* sv = (const float4*)sres;
#pragma unroll
    for (int i = 0; i < 6; ++i) {
        int t = tid + i * 256;
        outv[t] = sv[t];
    }
    if (tid < 1568 - 6 * 256) {
        int t = tid + 6 * 256;
        outv[t] = sv[t];
    }
}

extern "C" void kernel_launch(void* const* d_in, const int* in_sizes, int n_in,
                              void* d_out, int out_size) {
    const float* input = (const float*)d_in[0];   // [4,256,64,64] fp32
    const float* rois  = (const float*)d_in[1];   // [2048,5] fp32
    float* out = (float*)d_out;                   // [2048,256,7,7] fp32

    dim3 tgrid((HF * WF) / 32, CC / 32, NB);      // (128, 8, 4)
    transpose_nchw_nhwc<<<tgrid, dim3(32, 8)>>>(input);

    const int blocks = NB * (HF / 2) * (WF / 2) * (CC / 4);  // 262144 threads
    build_pyramid<<<(blocks + 255) / 256, 256>>>();

    roipool_kernel<<<dim3(2, KK), 256>>>(rois, out);
}

// round 10
// speedup vs baseline: 1.4043x; 1.4043x over previous
#include <cuda_runtime.h>
#include <cstdint>

#define HF 64
#define WF 64
#define CC 256
#define NB 4
#define KK 2048

// NHWC feature map: [N][64][64][C] = 16 MB
__device__ float g_nhwc[NB * HF * WF * CC];
// Row-pair max:  H1[n][h2][w][c] = max over rows {2h2, 2h2+1}   (8 MB)
__device__ float g_h1[NB * (HF / 2) * WF * CC];
// 2x2 block max: HW[n][h2][w2][c]                                (4 MB)
__device__ float g_hw[NB * (HF / 2) * (WF / 2) * CC];

__device__ __forceinline__ float4 fmax4(float4 a, float4 b) {
    a.x = fmaxf(a.x, b.x);
    a.y = fmaxf(a.y, b.y);
    a.z = fmaxf(a.z, b.z);
    a.w = fmaxf(a.w, b.w);
    return a;
}

// ---------------------------------------------------------------------------
// Kernel 1 (fused prologue): NCHW -> NHWC transpose + H1 + HW in one pass.
// Block = 32 channels x 2 full rows (128 spatial). smem tile [c=32][s=129-pad].
// grid = (HF/2, CC/32, NB) = (32, 8, 4); 256 threads (32 x 8).
// ---------------------------------------------------------------------------
__global__ void transpose_build(const float* __restrict__ in) {
    __shared__ float tile[32][129];   // stride 129: odd -> conflict-free columns
    const int n  = blockIdx.z;
    const int c0 = blockIdx.y * 32;
    const int h2 = blockIdx.x;
    const int s0 = h2 * 128;          // s = h*WF + w; two rows = 128 contiguous s

    const int sx = threadIdx.x;       // 0..31
    const int cy = threadIdx.y;       // 0..7

    const float* inp = in + (size_t)n * CC * (HF * WF);
#pragma unroll
    for (int j = 0; j < 32; j += 8) {
#pragma unroll
        for (int i = 0; i < 128; i += 32) {
            tile[cy + j][i + sx] =
                inp[(size_t)(c0 + cy + j) * (HF * WF) + s0 + i + sx];
        }
    }
    __syncthreads();

    // NHWC write: lane = channel, column read stride 129 (conflict-free)
    float* outp = g_nhwc + ((size_t)n * (HF * WF) + s0) * CC + c0;
#pragma unroll
    for (int i = 0; i < 16; ++i) {
        const int s = cy * 16 + i;
        outp[(size_t)s * CC + sx] = tile[sx][s];
    }
    // H1: max over the two rows, per w
    float* h1p = g_h1 + ((size_t)n * (HF / 2) + h2) * ((size_t)WF * CC) + c0;
#pragma unroll
    for (int i = 0; i < 8; ++i) {
        const int w = cy * 8 + i;
        h1p[(size_t)w * CC + sx] = fmaxf(tile[sx][w], tile[sx][64 + w]);
    }
    // HW: 2x2 block max
    float* hwp = g_hw + ((size_t)n * (HF / 2) + h2) * ((size_t)(WF / 2) * CC) + c0;
#pragma unroll
    for (int i = 0; i < 4; ++i) {
        const int w2 = cy * 4 + i;
        hwp[(size_t)w2 * CC + sx] =
            fmaxf(fmaxf(tile[sx][2 * w2],      tile[sx][2 * w2 + 1]),
                  fmaxf(tile[sx][64 + 2 * w2], tile[sx][64 + 2 * w2 + 1]));
    }
}

// ---------------------------------------------------------------------------
// Kernel 2: RoI max pool (R8 structure).
//   grid = (2 channel-halves, 2048 rois), block = 256 threads
//   cg = tid&31 (4 channels, float4), sl = tid>>5 (warp-uniform bin slice)
// h-range: odd lead row (orig) + aligned row-pairs + tail row (orig).
// Pair rows use HW col-pairs with the w-decomposition hoisted per bin;
// lead/tail rows keep R8's plain fine w-pair loop on orig.
// ---------------------------------------------------------------------------
__global__ __launch_bounds__(256, 6)
void roipool_kernel(const float* __restrict__ rois, float* __restrict__ out) {
    __shared__ float sres[128 * 49];

    const int k    = blockIdx.y;
    const int half = blockIdx.x;
    const int tid  = threadIdx.x;
    const int cg   = tid & 31;
    const int sl   = tid >> 5;

    const float* r = rois + (size_t)k * 5;
    const int b   = (int)r[0];
    const int rsw = __float2int_rn(r[1] * 0.0625f);  // round-half-even == jnp.round
    const int rsh = __float2int_rn(r[2] * 0.0625f);
    const int rew = __float2int_rn(r[3] * 0.0625f);
    const int reh = __float2int_rn(r[4] * 0.0625f);
    const int roi_w = max(rew - rsw + 1, 1);
    const int roi_h = max(reh - rsh + 1, 1);

    // Reciprocal-multiply division matches the reference's XLA lowering
    // (verified R2: rel_err == 0). Do not change to exact divide.
    const float RCP7  = 1.0f / 7.0f;
    const float bin_h = (float)roi_h * RCP7;
    const float bin_w = (float)roi_w * RCP7;

    const int coff = half * 32 + cg;
    const float4* base   = (const float4*)g_nhwc + (size_t)b * (HF * WF) * 64 + coff;
    const float4* baseh  = (const float4*)g_h1  + (size_t)b * ((HF / 2) * WF) * 64 + coff;
    const float4* basehw = (const float4*)g_hw  + (size_t)b * ((HF / 2) * (WF / 2)) * 64 + coff;

    const float NEG_INF = __int_as_float(0xff800000);

    int bi           = (49 * sl) >> 3;        // 6,6,6,6,6,6,6,7 bins/slice
    const int bi_end = (49 * (sl + 1)) >> 3;

    for (; bi < bi_end; ++bi) {
        const int ph = bi / 7;
        const int pw = bi - ph * 7;

        int hstart = (int)floorf((float)ph * bin_h) + rsh;
        int hend   = (int)ceilf((float)(ph + 1) * bin_h) + rsh;
        hstart = min(max(hstart, 0), HF);
        hend   = min(max(hend, 0), HF);

        int wstart = (int)floorf((float)pw * bin_w) + rsw;
        int wend   = (int)ceilf((float)(pw + 1) * bin_w) + rsw;
        wstart = min(max(wstart, 0), WF);
        wend   = min(max(wend, 0), WF);

        float4 m0 = make_float4(NEG_INF, NEG_INF, NEG_INF, NEG_INF);
        float4 m1 = m0;
        const int wc = wend - wstart;
        const bool nonempty = (hstart < hend) && (wc > 0);

        if (nonempty) {
            // w-decomposition for pair rows, hoisted (bin-invariant):
            const int wl  = wstart & 1;          // fine lead col at wstart
            const int a   = wstart + wl;         // even
            const int w2s = a >> 1;
            const int w2e = w2s + ((wend - a) >> 1);
            const int wt  = (wend - a) & 1;      // fine tail col at wend-1

            int h = hstart;
            // odd lead row from orig (fine w-pair loop, R8 style)
            if (h & 1) {
                const float4* rowp = base + (size_t)(h * WF + wstart) * 64;
                int w = 0;
#pragma unroll 2
                for (; w + 2 <= wc; w += 2) {
                    float4 x = __ldg(rowp + (size_t)w * 64);
                    float4 y = __ldg(rowp + (size_t)(w + 1) * 64);
                    m0 = fmax4(m0, x);
                    m1 = fmax4(m1, y);
                }
                if (w < wc) m0 = fmax4(m0, __ldg(rowp + (size_t)w * 64));
                ++h;
            }
            // aligned row-pairs: lead/tail cols from H1, pairs from HW
            for (; h + 2 <= hend; h += 2) {
                const int h2 = h >> 1;
                const float4* rh1 = baseh  + (size_t)(h2 * WF) * 64;
                const float4* rhw = basehw + (size_t)(h2 * (WF / 2)) * 64;
                if (wl) m0 = fmax4(m0, __ldg(rh1 + (size_t)wstart * 64));
                int w2 = w2s;
#pragma unroll 2
                for (; w2 + 2 <= w2e; w2 += 2) {
                    float4 x = __ldg(rhw + (size_t)w2 * 64);
                    float4 y = __ldg(rhw + (size_t)(w2 + 1) * 64);
                    m0 = fmax4(m0, x);
                    m1 = fmax4(m1, y);
                }
                if (w2 < w2e) m1 = fmax4(m1, __ldg(rhw + (size_t)w2 * 64));
                if (wt) m1 = fmax4(m1, __ldg(rh1 + (size_t)(wend - 1) * 64));
            }
            // tail row from orig
            if (h < hend) {
                const float4* rowp = base + (size_t)(h * WF + wstart) * 64;
                int w = 0;
#pragma unroll 2
                for (; w + 2 <= wc; w += 2) {
                    float4 x = __ldg(rowp + (size_t)w * 64);
                    float4 y = __ldg(rowp + (size_t)(w + 1) * 64);
                    m0 = fmax4(m0, x);
                    m1 = fmax4(m1, y);
                }
                if (w < wc) m0 = fmax4(m0, __ldg(rowp + (size_t)w * 64));
            }
        }

        float4 m = fmax4(m0, m1);
        if (!nonempty) m = make_float4(0.f, 0.f, 0.f, 0.f);

        const int cbase = 4 * cg;
        sres[(cbase + 0) * 49 + bi] = m.x;
        sres[(cbase + 1) * 49 + bi] = m.y;
        sres[(cbase + 2) * 49 + bi] = m.z;
        sres[(cbase + 3) * 49 + bi] = m.w;
    }
    __syncthreads();

    // Contiguous coalesced flush: block owns output span
    // [k*12544 + half*6272, +6272) = 1568 float4.
    float4* outv = (float4*)(out + (size_t)k * (CC * 49) + (size_t)half * (128 * 49));
    const float4* sv = (const float4*)sres;
#pragma unroll
    for (int i = 0; i < 6; ++i) {
        int t = tid + i * 256;
        outv[t] = sv[t];
    }
    if (tid < 1568 - 6 * 256) {
        int t = tid + 6 * 256;
        outv[t] = sv[t];
    }
}

extern "C" void kernel_launch(void* const* d_in, const int* in_sizes, int n_in,
                              void* d_out, int out_size) {
    const float* input = (const float*)d_in[0];   // [4,256,64,64] fp32
    const float* rois  = (const float*)d_in[1];   // [2048,5] fp32
    float* out = (float*)d_out;                   // [2048,256,7,7] fp32

    transpose_build<<<dim3(HF / 2, CC / 32, NB), dim3(32, 8)>>>(input);

    roipool_kernel<<<dim3(2, KK), 256>>>(rois, out);
}

// round 11
// speedup vs baseline: 1.5019x; 1.0695x over previous
#include <cuda_runtime.h>
#include <cstdint>

#define HF 64
#define WF 64
#define CC 256
#define NB 4
#define KK 2048

// NHWC feature map: [N][64][64][C] = 16 MB
__device__ float g_nhwc[NB * HF * WF * CC];
// Row-pair max: H1[n][h2][w][c] = max over rows {2h2, 2h2+1}   (8 MB)
__device__ float g_h1[NB * (HF / 2) * WF * CC];

__device__ __forceinline__ float4 fmax4(float4 a, float4 b) {
    a.x = fmaxf(a.x, b.x);
    a.y = fmaxf(a.y, b.y);
    a.z = fmaxf(a.z, b.z);
    a.w = fmaxf(a.w, b.w);
    return a;
}

// ---------------------------------------------------------------------------
// Kernel 1 (fused prologue, measured 6.9 us in R10): NCHW -> NHWC transpose
// + H1 row-pair max in one pass. Block = 32 channels x 2 full rows.
// grid = (HF/2, CC/32, NB) = (32, 8, 4); 256 threads (32 x 8).
// ---------------------------------------------------------------------------
__global__ void transpose_build(const float* __restrict__ in) {
    __shared__ float tile[32][129];   // stride 129: odd -> conflict-free columns
    const int n  = blockIdx.z;
    const int c0 = blockIdx.y * 32;
    const int h2 = blockIdx.x;
    const int s0 = h2 * 128;          // s = h*WF + w; two rows = 128 contiguous s

    const int sx = threadIdx.x;       // 0..31
    const int cy = threadIdx.y;       // 0..7

    const float* inp = in + (size_t)n * CC * (HF * WF);
#pragma unroll
    for (int j = 0; j < 32; j += 8) {
#pragma unroll
        for (int i = 0; i < 128; i += 32) {
            tile[cy + j][i + sx] =
                inp[(size_t)(c0 + cy + j) * (HF * WF) + s0 + i + sx];
        }
    }
    __syncthreads();

    // NHWC write: lane = channel (coalesced), column read stride 129
    float* outp = g_nhwc + ((size_t)n * (HF * WF) + s0) * CC + c0;
#pragma unroll
    for (int i = 0; i < 16; ++i) {
        const int s = cy * 16 + i;
        outp[(size_t)s * CC + sx] = tile[sx][s];
    }
    // H1: max over the two rows, per w
    float* h1p = g_h1 + ((size_t)n * (HF / 2) + h2) * ((size_t)WF * CC) + c0;
#pragma unroll
    for (int i = 0; i < 8; ++i) {
        const int w = cy * 8 + i;
        h1p[(size_t)w * CC + sx] = fmaxf(tile[sx][w], tile[sx][64 + w]);
    }
}

// ---------------------------------------------------------------------------
// Kernel 2: RoI max pool — exact R8 structure (measured best: ~93 us).
//   grid = (2 channel-halves, 2048 rois), block = 256 threads
//   cg = tid&31 (4 channels, float4), sl = tid>>5 (warp-uniform bin slice)
// h-loop: odd lead row (orig) + aligned row-pairs (H1) + tail row (orig).
// ---------------------------------------------------------------------------
__global__ __launch_bounds__(256, 6)
void roipool_kernel(const float* __restrict__ rois, float* __restrict__ out) {
    __shared__ float sres[128 * 49];

    const int k    = blockIdx.y;
    const int half = blockIdx.x;
    const int tid  = threadIdx.x;
    const int cg   = tid & 31;
    const int sl   = tid >> 5;

    const float* r = rois + (size_t)k * 5;
    const int b   = (int)r[0];
    const int rsw = __float2int_rn(r[1] * 0.0625f);  // round-half-even == jnp.round
    const int rsh = __float2int_rn(r[2] * 0.0625f);
    const int rew = __float2int_rn(r[3] * 0.0625f);
    const int reh = __float2int_rn(r[4] * 0.0625f);
    const int roi_w = max(rew - rsw + 1, 1);
    const int roi_h = max(reh - rsh + 1, 1);

    // Reciprocal-multiply division matches the reference's XLA lowering
    // (verified R2: rel_err == 0). Do not change to exact divide.
    const float RCP7  = 1.0f / 7.0f;
    const float bin_h = (float)roi_h * RCP7;
    const float bin_w = (float)roi_w * RCP7;

    const int coff = half * 32 + cg;
    const float4* base  = (const float4*)g_nhwc + (size_t)b * (HF * WF) * 64 + coff;
    const float4* baseh = (const float4*)g_h1  + (size_t)b * ((HF / 2) * WF) * 64 + coff;

    const float NEG_INF = __int_as_float(0xff800000);

    int bi           = (49 * sl) >> 3;        // 6,6,6,6,6,6,6,7 bins/slice
    const int bi_end = (49 * (sl + 1)) >> 3;

    for (; bi < bi_end; ++bi) {
        const int ph = bi / 7;
        const int pw = bi - ph * 7;

        int hstart = (int)floorf((float)ph * bin_h) + rsh;
        int hend   = (int)ceilf((float)(ph + 1) * bin_h) + rsh;
        hstart = min(max(hstart, 0), HF);
        hend   = min(max(hend, 0), HF);

        int wstart = (int)floorf((float)pw * bin_w) + rsw;
        int wend   = (int)ceilf((float)(pw + 1) * bin_w) + rsw;
        wstart = min(max(wstart, 0), WF);
        wend   = min(max(wend, 0), WF);

        float4 m0 = make_float4(NEG_INF, NEG_INF, NEG_INF, NEG_INF);
        float4 m1 = m0;
        const int wc = wend - wstart;

        int h = hstart;
        // odd lead row from orig
        if ((h & 1) && h < hend) {
            const float4* rowp = base + (size_t)(h * WF + wstart) * 64;
            int w = 0;
#pragma unroll 2
            for (; w + 2 <= wc; w += 2) {
                float4 a = __ldg(rowp + (size_t)w * 64);
                float4 c = __ldg(rowp + (size_t)(w + 1) * 64);
                m0 = fmax4(m0, a);
                m1 = fmax4(m1, c);
            }
            if (w < wc) m0 = fmax4(m0, __ldg(rowp + (size_t)w * 64));
            ++h;
        }
        // aligned pairs from H1
        {
            const float4* rowp = baseh + (size_t)((h >> 1) * WF + wstart) * 64;
            for (; h + 2 <= hend; h += 2) {
                int w = 0;
#pragma unroll 2
                for (; w + 2 <= wc; w += 2) {
                    float4 a = __ldg(rowp + (size_t)w * 64);
                    float4 c = __ldg(rowp + (size_t)(w + 1) * 64);
                    m0 = fmax4(m0, a);
                    m1 = fmax4(m1, c);
                }
                if (w < wc) m0 = fmax4(m0, __ldg(rowp + (size_t)w * 64));
                rowp += (size_t)WF * 64;
            }
        }
        // tail row from orig
        if (h < hend) {
            const float4* rowp = base + (size_t)(h * WF + wstart) * 64;
            int w = 0;
#pragma unroll 2
            for (; w + 2 <= wc; w += 2) {
                float4 a = __ldg(rowp + (size_t)w * 64);
                float4 c = __ldg(rowp + (size_t)(w + 1) * 64);
                m0 = fmax4(m0, a);
                m1 = fmax4(m1, c);
            }
            if (w < wc) m0 = fmax4(m0, __ldg(rowp + (size_t)w * 64));
        }

        float4 m = fmax4(m0, m1);
        if (!((hstart < hend) && (wstart < wend)))
            m = make_float4(0.f, 0.f, 0.f, 0.f);

        const int cbase = 4 * cg;
        sres[(cbase + 0) * 49 + bi] = m.x;
        sres[(cbase + 1) * 49 + bi] = m.y;
        sres[(cbase + 2) * 49 + bi] = m.z;
        sres[(cbase + 3) * 49 + bi] = m.w;
    }
    __syncthreads();

    // Contiguous coalesced flush: block owns output span
    // [k*12544 + half*6272, +6272) = 1568 float4.
    float4* outv = (float4*)(out + (size_t)k * (CC * 49) + (size_t)half * (128 * 49));
    const float4* sv = (const float4*)sres;
#pragma unroll
    for (int i = 0; i < 6; ++i) {
        int t = tid + i * 256;
        outv[t] = sv[t];
    }
    if (tid < 1568 - 6 * 256) {
        int t = tid + 6 * 256;
        outv[t] = sv[t];
    }
}

extern "C" void kernel_launch(void* const* d_in, const int* in_sizes, int n_in,
                              void* d_out, int out_size) {
    const float* input = (const float*)d_in[0];   // [4,256,64,64] fp32
    const float* rois  = (const float*)d_in[1];   // [2048,5] fp32
    float* out = (float*)d_out;                   // [2048,256,7,7] fp32

    transpose_build<<<dim3(HF / 2, CC / 32, NB), dim3(32, 8)>>>(input);

    roipool_kernel<<<dim3(2, KK), 256>>>(rois, out);
}

// round 12
// speedup vs baseline: 1.5707x; 1.0459x over previous
#include <cuda_runtime.h>
#include <cstdint>

#define HF 64
#define WF 64
#define CC 256
#define NB 4
#define KK 2048

// NHWC feature map: [N][64][64][C] = 16 MB
__device__ float g_nhwc[NB * HF * WF * CC];
// Row-pair max: H1[n][h2][w][c] = max over rows {2h2, 2h2+1}   (8 MB)
__device__ float g_h1[NB * (HF / 2) * WF * CC];
// Per-(roi,bin) window bounds, packed: (hs, he, ws, we)         (1.6 MB)
__device__ int4 g_bounds[KK * 49];

__device__ __forceinline__ float4 fmax4(float4 a, float4 b) {
    a.x = fmaxf(a.x, b.x);
    a.y = fmaxf(a.y, b.y);
    a.z = fmaxf(a.z, b.z);
    a.w = fmaxf(a.w, b.w);
    return a;
}

// ---------------------------------------------------------------------------
// Kernel 0: per-(roi,bin) bounds. 100352 threads, ~2 us.
// ---------------------------------------------------------------------------
__global__ void compute_bounds(const float* __restrict__ rois) {
    const int i = blockIdx.x * blockDim.x + threadIdx.x;
    if (i >= KK * 49) return;
    const int k  = i / 49;
    const int bi = i - k * 49;
    const int ph = bi / 7;
    const int pw = bi - ph * 7;

    const float* r = rois + (size_t)k * 5;
    const int rsw = __float2int_rn(r[1] * 0.0625f);  // round-half-even == jnp.round
    const int rsh = __float2int_rn(r[2] * 0.0625f);
    const int rew = __float2int_rn(r[3] * 0.0625f);
    const int reh = __float2int_rn(r[4] * 0.0625f);
    // Reciprocal-multiply division matches the reference's XLA lowering
    // (verified R2: rel_err == 0). Do not change to exact divide.
    const float RCP7  = 1.0f / 7.0f;
    const float bin_h = (float)max(reh - rsh + 1, 1) * RCP7;
    const float bin_w = (float)max(rew - rsw + 1, 1) * RCP7;

    int hs = min(max((int)floorf((float)ph * bin_h) + rsh, 0), HF);
    int he = min(max((int)ceilf((float)(ph + 1) * bin_h) + rsh, 0), HF);
    int ws = min(max((int)floorf((float)pw * bin_w) + rsw, 0), WF);
    int we = min(max((int)ceilf((float)(pw + 1) * bin_w) + rsw, 0), WF);

    g_bounds[i] = make_int4(hs, he, ws, we);
}

// ---------------------------------------------------------------------------
// Kernel 1 (fused prologue, measured ~7 us): NCHW -> NHWC transpose + H1
// row-pair max in one pass. grid = (HF/2, CC/32, NB); 256 threads (32 x 8).
// ---------------------------------------------------------------------------
__global__ void transpose_build(const float* __restrict__ in) {
    __shared__ float tile[32][129];   // stride 129: odd -> conflict-free columns
    const int n  = blockIdx.z;
    const int c0 = blockIdx.y * 32;
    const int h2 = blockIdx.x;
    const int s0 = h2 * 128;          // s = h*WF + w; two rows = 128 contiguous s

    const int sx = threadIdx.x;       // 0..31
    const int cy = threadIdx.y;       // 0..7

    const float* inp = in + (size_t)n * CC * (HF * WF);
#pragma unroll
    for (int j = 0; j < 32; j += 8) {
#pragma unroll
        for (int i = 0; i < 128; i += 32) {
            tile[cy + j][i + sx] =
                inp[(size_t)(c0 + cy + j) * (HF * WF) + s0 + i + sx];
        }
    }
    __syncthreads();

    float* outp = g_nhwc + ((size_t)n * (HF * WF) + s0) * CC + c0;
#pragma unroll
    for (int i = 0; i < 16; ++i) {
        const int s = cy * 16 + i;
        outp[(size_t)s * CC + sx] = tile[sx][s];
    }
    float* h1p = g_h1 + ((size_t)n * (HF / 2) + h2) * ((size_t)WF * CC) + c0;
#pragma unroll
    for (int i = 0; i < 8; ++i) {
        const int w = cy * 8 + i;
        h1p[(size_t)w * CC + sx] = fmaxf(tile[sx][w], tile[sx][64 + w]);
    }
}

// ---------------------------------------------------------------------------
// Kernel 2: RoI max pool (R8/R11 structure, bounds from precomputed table).
//   grid = (2 channel-halves, 2048 rois), block = 256 threads
//   cg = tid&31 (4 channels, float4), sl = tid>>5 (warp-uniform bin slice)
// h-loop: odd lead row (orig) + aligned row-pairs (H1) + tail row (orig).
// ---------------------------------------------------------------------------
__global__ __launch_bounds__(256, 6)
void roipool_kernel(const float* __restrict__ rois, float* __restrict__ out) {
    __shared__ float sres[128 * 49];

    const int k    = blockIdx.y;
    const int half = blockIdx.x;
    const int tid  = threadIdx.x;
    const int cg   = tid & 31;
    const int sl   = tid >> 5;

    const int b = (int)__ldg(rois + (size_t)k * 5);

    const int coff = half * 32 + cg;
    const float4* base  = (const float4*)g_nhwc + (size_t)b * (HF * WF) * 64 + coff;
    const float4* baseh = (const float4*)g_h1  + (size_t)b * ((HF / 2) * WF) * 64 + coff;

    const float NEG_INF = __int_as_float(0xff800000);

    int bi           = (49 * sl) >> 3;        // 6,6,6,6,6,6,6,7 bins/slice
    const int bi_end = (49 * (sl + 1)) >> 3;

    for (; bi < bi_end; ++bi) {
        // one uniform LDG.128 replaces the per-bin boundary math
        const int4 bb = __ldg(&g_bounds[k * 49 + bi]);
        const int hstart = bb.x, hend = bb.y, wstart = bb.z, wend = bb.w;

        float4 m0 = make_float4(NEG_INF, NEG_INF, NEG_INF, NEG_INF);
        float4 m1 = m0;
        const int wc = wend - wstart;

        int h = hstart;
        // odd lead row from orig
        if ((h & 1) && h < hend) {
            const float4* rowp = base + (size_t)(h * WF + wstart) * 64;
            int w = 0;
#pragma unroll 2
            for (; w + 2 <= wc; w += 2) {
                float4 a = __ldg(rowp + (size_t)w * 64);
                float4 c = __ldg(rowp + (size_t)(w + 1) * 64);
                m0 = fmax4(m0, a);
                m1 = fmax4(m1, c);
            }
            if (w < wc) m0 = fmax4(m0, __ldg(rowp + (size_t)w * 64));
            ++h;
        }
        // aligned pairs from H1
        {
            const float4* rowp = baseh + (size_t)((h >> 1) * WF + wstart) * 64;
            for (; h + 2 <= hend; h += 2) {
                int w = 0;
#pragma unroll 2
                for (; w + 2 <= wc; w += 2) {
                    float4 a = __ldg(rowp + (size_t)w * 64);
                    float4 c = __ldg(rowp + (size_t)(w + 1) * 64);
                    m0 = fmax4(m0, a);
                    m1 = fmax4(m1, c);
                }
                if (w < wc) m0 = fmax4(m0, __ldg(rowp + (size_t)w * 64));
                rowp += (size_t)WF * 64;
            }
        }
        // tail row from orig
        if (h < hend) {
            const float4* rowp = base + (size_t)(h * WF + wstart) * 64;
            int w = 0;
#pragma unroll 2
            for (; w + 2 <= wc; w += 2) {
                float4 a = __ldg(rowp + (size_t)w * 64);
                float4 c = __ldg(rowp + (size_t)(w + 1) * 64);
                m0 = fmax4(m0, a);
                m1 = fmax4(m1, c);
            }
            if (w < wc) m0 = fmax4(m0, __ldg(rowp + (size_t)w * 64));
        }

        float4 m = fmax4(m0, m1);
        if (!((hstart < hend) && (wstart < wend)))
            m = make_float4(0.f, 0.f, 0.f, 0.f);

        const int cbase = 4 * cg;
        sres[(cbase + 0) * 49 + bi] = m.x;
        sres[(cbase + 1) * 49 + bi] = m.y;
        sres[(cbase + 2) * 49 + bi] = m.z;
        sres[(cbase + 3) * 49 + bi] = m.w;
    }
    __syncthreads();

    // Contiguous coalesced flush: block owns output span
    // [k*12544 + half*6272, +6272) = 1568 float4.
    float4* outv = (float4*)(out + (size_t)k * (CC * 49) + (size_t)half * (128 * 49));
    const float4* sv = (const float4*)sres;
#pragma unroll
    for (int i = 0; i < 6; ++i) {
        int t = tid + i * 256;
        outv[t] = sv[t];
    }
    if (tid < 1568 - 6 * 256) {
        int t = tid + 6 * 256;
        outv[t] = sv[t];
    }
}

extern "C" void kernel_launch(void* const* d_in, const int* in_sizes, int n_in,
                              void* d_out, int out_size) {
    const float* input = (const float*)d_in[0];   // [4,256,64,64] fp32
    const float* rois  = (const float*)d_in[1];   // [2048,5] fp32
    float* out = (float*)d_out;                   // [2048,256,7,7] fp32

    compute_bounds<<<(KK * 49 + 255) / 256, 256>>>(rois);
    transpose_build<<<dim3(HF / 2, CC / 32, NB), dim3(32, 8)>>>(input);

    roipool_kernel<<<dim3(2, KK), 256>>>(rois, out);
}